// round 5
// baseline (speedup 1.0000x reference)
#include <cuda_runtime.h>
#include <cuda_bf16.h>
#include <math.h>
#include <stdint.h>

#define N_INST 32768
#define D      2048
#define DP     512
#define CLASSES 4

#define TM 256            // instances per CTA
#define TN 128            // j per CTA
#define NSTAGE 4
#define ASTG 16384        // 256 rows * 64B
#define BSTG 8192         // 128 rows * 64B
#define STG  24576
#define NSTOT 96          // 3 passes * 32 k-tiles

// ---------------- scratch (module-scope, no runtime allocation) ----------------
__device__ __align__(128) int8_t g_Vhi[(size_t)N_INST * D];
__device__ __align__(128) int8_t g_Vlo[(size_t)N_INST * D];
__device__ __align__(128) int8_t g_Uhi[DP * D];
__device__ __align__(128) int8_t g_Ulo[DP * D];
__device__ float g_sV[N_INST];
__device__ float g_sU[DP];
__device__ float g_Sp[4][N_INST];
__device__ float g_S[N_INST];
__device__ float g_A[N_INST];
__device__ float g_bm[64], g_bz[64], g_MZ[2];
__device__ float g_tp[64][D];
__device__ float g_t[D];

// ---------------- PTX helpers (plain sm_80-era features only) ----------------
static __device__ __forceinline__ uint32_t smem_u32(const void* p) {
    uint32_t a;
    asm("{ .reg .u64 t; cvta.to.shared.u64 t, %1; cvt.u32.u64 %0, t; }" : "=r"(a) : "l"(p));
    return a;
}
static __device__ __forceinline__ void cp16(uint32_t dst, const void* src) {
    asm volatile("cp.async.cg.shared.global [%0], [%1], 16;" :: "r"(dst), "l"(src) : "memory");
}
static __device__ __forceinline__ void ldsm4(uint32_t* r, uint32_t addr) {
    asm volatile("ldmatrix.sync.aligned.m8n8.x4.shared.b16 {%0,%1,%2,%3}, [%4];"
                 : "=r"(r[0]), "=r"(r[1]), "=r"(r[2]), "=r"(r[3]) : "r"(addr));
}
static __device__ __forceinline__ void imma(int* d, const uint32_t* a, uint32_t b0, uint32_t b1) {
    asm volatile("mma.sync.aligned.m16n8k32.row.col.s32.s8.s8.s32 "
                 "{%0,%1,%2,%3}, {%4,%5,%6,%7}, {%8,%9}, {%0,%1,%2,%3};"
                 : "+r"(d[0]), "+r"(d[1]), "+r"(d[2]), "+r"(d[3])
                 : "r"(a[0]), "r"(a[1]), "r"(a[2]), "r"(a[3]), "r"(b0), "r"(b1));
}

// ---------------- pack: fp32 -> per-row 16-bit fixed point (s8 hi, s8 lo) ----------------
static __device__ __forceinline__ void quant4(float4 v, float inv, char4& hi, char4& lo) {
    int q0 = __float2int_rn(v.x * inv), q1 = __float2int_rn(v.y * inv);
    int q2 = __float2int_rn(v.z * inv), q3 = __float2int_rn(v.w * inv);
    int h0 = (q0 + 128) >> 8, h1 = (q1 + 128) >> 8, h2 = (q2 + 128) >> 8, h3 = (q3 + 128) >> 8;
    hi = make_char4((char)h0, (char)h1, (char)h2, (char)h3);
    lo = make_char4((char)(q0 - (h0 << 8)), (char)(q1 - (h1 << 8)),
                    (char)(q2 - (h2 << 8)), (char)(q3 - (h3 << 8)));
}

template <bool ISV>
static __device__ __forceinline__ void pack_row(const float* __restrict__ src,
                                                int8_t* __restrict__ hiB, int8_t* __restrict__ loB,
                                                float* __restrict__ scale, int row) {
    __shared__ float mx[256];
    const int tid = threadIdx.x;
    const float4* s4 = (const float4*)(src + (size_t)row * D);
    float4 a = s4[tid], b = s4[tid + 256];
    float m = fmaxf(fmaxf(fabsf(a.x), fabsf(a.y)), fmaxf(fabsf(a.z), fabsf(a.w)));
    m = fmaxf(m, fmaxf(fmaxf(fabsf(b.x), fabsf(b.y)), fmaxf(fabsf(b.z), fabsf(b.w))));
    mx[tid] = m; __syncthreads();
    for (int s = 128; s > 0; s >>= 1) {
        if (tid < s) mx[tid] = fmaxf(mx[tid], mx[tid + s]);
        __syncthreads();
    }
    float mxv = fmaxf(mx[0], 1e-30f);
    float inv = 32512.f / mxv;
    char4 h, l;
    quant4(a, inv, h, l);
    ((char4*)hiB)[(size_t)row * 512 + tid] = h;
    ((char4*)loB)[(size_t)row * 512 + tid] = l;
    quant4(b, inv, h, l);
    ((char4*)hiB)[(size_t)row * 512 + tid + 256] = h;
    ((char4*)loB)[(size_t)row * 512 + tid + 256] = l;
    if (tid == 0) scale[row] = (mxv / 32512.f) * 256.f;
}

__global__ __launch_bounds__(256) void k_packV(const float* __restrict__ V) {
    pack_row<true>(V, g_Vhi, g_Vlo, g_sV, blockIdx.x);
}
__global__ __launch_bounds__(256) void k_packU(const float* __restrict__ U) {
    pack_row<false>(U, g_Uhi, g_Ulo, g_sU, blockIdx.x);
}

// ---------------- main GEMM: C[256x128] int8 3-pass, fused w*tanh fold ----------------
// smem: 4 stages (A 256x64B + B 128x64B, xor-swizzled) | X master s32[256][128] | scales.
// Pass 0: Vhi*Ulo, pass 1: Vlo*Uhi (same s32 acc, weight 256, parked to smem),
// pass 2: Vhi*Uhi (weight 65536).  C = sVs*sUs*(H + X/256), sVs/sUs carry the 256 factors.
#define X_OFF   (NSTAGE * STG)          // 98304
#define SC_OFF  (X_OFF + 131072)        // 229376: Wsh 512 | sU 512 | sV 1024
#define SMEM_BYTES (SC_OFF + 2048 + 128)

__global__ __launch_bounds__(512, 1) void k_scores_tc(const float* __restrict__ Wm)
{
    extern __shared__ uint8_t dsm[];
    uint32_t raw = smem_u32(dsm);
    uint32_t sb  = (raw + 127) & ~127u;
    uint8_t* sp  = dsm + (sb - raw);
    int*   Xs  = (int*)(sp + X_OFF);
    float* Wsh = (float*)(sp + SC_OFF);
    float* sUs = (float*)(sp + SC_OFF + 512);
    float* sVs = (float*)(sp + SC_OFF + 1024);

    const int tid  = threadIdx.x;
    const int lane = tid & 31, wid = tid >> 5;
    const int wm = wid & 3, wn = wid >> 2;
    const int ibase = blockIdx.x * TM;
    const int jbase = blockIdx.y * TN;

    if (tid < TN) { Wsh[tid] = Wm[jbase + tid]; sUs[tid] = g_sU[jbase + tid]; }
    if (tid < TM) sVs[tid] = g_sV[ibase + tid];

    const size_t aoff = (size_t)ibase * D;
    const size_t boff = (size_t)jbase * D;
    const int8_t* aP[3] = { g_Vhi + aoff, g_Vlo + aoff, g_Vhi + aoff };
    const int8_t* bP[3] = { g_Ulo + boff, g_Uhi + boff, g_Uhi + boff };

    int acc[4][4][4];
    #pragma unroll
    for (int a = 0; a < 4; ++a)
        #pragma unroll
        for (int b = 0; b < 4; ++b)
            #pragma unroll
            for (int c = 0; c < 4; ++c) acc[a][b][c] = 0;

    auto load_stage = [&](int s) {
        const int pass = s >> 5, kt = s & 31;
        const int8_t* srcA = aP[pass] + kt * 64;
        const int8_t* srcB = bP[pass] + kt * 64;
        const uint32_t dA = sb + (s & 3) * STG;
        const uint32_t dB = dA + ASTG;
        #pragma unroll
        for (int q = 0; q < 2; ++q) {
            uint32_t chunk = tid + q * 512;
            uint32_t row = chunk >> 2, cb = chunk & 3;
            cp16(dA + row * 64 + ((cb ^ (row >> 1)) & 3) * 16,
                 srcA + (size_t)row * D + cb * 16);
        }
        {
            uint32_t row = tid >> 2, cb = tid & 3;
            cp16(dB + row * 64 + ((cb ^ (row >> 1)) & 3) * 16,
                 srcB + (size_t)row * D + cb * 16);
        }
        asm volatile("cp.async.commit_group;" ::: "memory");
    };

    load_stage(0); load_stage(1); load_stage(2);

    const int gr = lane >> 2;
    const int gc = (lane & 3) * 2;
    const uint32_t rlocA = (lane & 7) + ((lane >> 3) & 1) * 8;
    const uint32_t cbl   = (lane >> 4) & 1;

    #pragma unroll 1
    for (int s = 0; s < NSTOT; ++s) {
        if (s == 64) {   // park cross-term accumulators (weight 256) into smem master
            #pragma unroll
            for (int mt = 0; mt < 4; ++mt) {
                int r0 = wm * 64 + mt * 16 + gr;
                #pragma unroll
                for (int nt = 0; nt < 4; ++nt) {
                    int c0 = wn * 32 + nt * 8 + gc;
                    Xs[r0 * TN + c0]           = acc[mt][nt][0];
                    Xs[r0 * TN + c0 + 1]       = acc[mt][nt][1];
                    Xs[(r0 + 8) * TN + c0]     = acc[mt][nt][2];
                    Xs[(r0 + 8) * TN + c0 + 1] = acc[mt][nt][3];
                    acc[mt][nt][0] = acc[mt][nt][1] = acc[mt][nt][2] = acc[mt][nt][3] = 0;
                }
            }
        }
        asm volatile("cp.async.wait_group 2;" ::: "memory");
        __syncthreads();
        const uint32_t smA = sb + (s & 3) * STG;
        const uint32_t smB = smA + ASTG;

        #pragma unroll
        for (int kk = 0; kk < 2; ++kk) {
            const uint32_t cb = cbl + kk * 2;
            uint32_t Af[4][4], Bf[2][4];
            #pragma unroll
            for (int mt = 0; mt < 4; ++mt) {
                uint32_t r = wm * 64 + mt * 16 + rlocA;
                ldsm4(Af[mt], smA + r * 64 + ((cb ^ (r >> 1)) & 3) * 16);
            }
            #pragma unroll
            for (int p = 0; p < 2; ++p) {
                uint32_t r = wn * 32 + p * 16 + rlocA;
                ldsm4(Bf[p], smB + r * 64 + ((cb ^ (r >> 1)) & 3) * 16);
            }
            #pragma unroll
            for (int mt = 0; mt < 4; ++mt)
                #pragma unroll
                for (int nt = 0; nt < 4; ++nt) {
                    const uint32_t* B = Bf[nt >> 1];
                    imma(acc[mt][nt], Af[mt],
                         (nt & 1) ? B[1] : B[0], (nt & 1) ? B[3] : B[2]);
                }
        }
        if (s + 3 < NSTOT) load_stage(s + 3);
    }

    // ---- epilogue: S_part[i] = sum_j w_j * tanh(sVs_i*sUs_j*(H + X/256)) ----
    __syncthreads();
    float* part = (float*)sp;   // overlays stage buffers (done with them)

    #pragma unroll
    for (int mt = 0; mt < 4; ++mt) {
        int r0 = wm * 64 + mt * 16 + gr;
        float sv0 = sVs[r0], sv1 = sVs[r0 + 8];
        float l0 = 0.f, l1 = 0.f;
        #pragma unroll
        for (int nt = 0; nt < 4; ++nt) {
            int c0 = wn * 32 + nt * 8 + gc;
            float su0 = sUs[c0], su1 = sUs[c0 + 1];
            float w0 = Wsh[c0],  w1 = Wsh[c0 + 1];
            float x00 = (float)Xs[r0 * TN + c0]           * 0.00390625f;
            float x01 = (float)Xs[r0 * TN + c0 + 1]       * 0.00390625f;
            float x10 = (float)Xs[(r0 + 8) * TN + c0]     * 0.00390625f;
            float x11 = (float)Xs[(r0 + 8) * TN + c0 + 1] * 0.00390625f;
            l0 += w0 * tanhf(((float)acc[mt][nt][0] + x00) * (sv0 * su0))
                + w1 * tanhf(((float)acc[mt][nt][1] + x01) * (sv0 * su1));
            l1 += w0 * tanhf(((float)acc[mt][nt][2] + x10) * (sv1 * su0))
                + w1 * tanhf(((float)acc[mt][nt][3] + x11) * (sv1 * su1));
        }
        l0 += __shfl_xor_sync(0xffffffffu, l0, 1);
        l0 += __shfl_xor_sync(0xffffffffu, l0, 2);
        l1 += __shfl_xor_sync(0xffffffffu, l1, 1);
        l1 += __shfl_xor_sync(0xffffffffu, l1, 2);
        if ((lane & 3) == 0) {
            part[wn * 256 + wm * 64 + mt * 16 + gr]     = l0;
            part[wn * 256 + wm * 64 + mt * 16 + 8 + gr] = l1;
        }
    }
    __syncthreads();
    if (tid < TM) {
        float sv = part[tid] + part[256 + tid] + part[512 + tid] + part[768 + tid];
        g_Sp[blockIdx.y][ibase + tid] = sv;
    }
}

// ---------------- parallel softmax (3 tiny kernels) ----------------
__global__ __launch_bounds__(512) void k_smax1() {
    __shared__ float sm[512];
    const int tid = threadIdx.x;
    const int i = blockIdx.x * 512 + tid;
    float s = g_Sp[0][i] + g_Sp[1][i] + g_Sp[2][i] + g_Sp[3][i];
    g_S[i] = s;
    sm[tid] = s; __syncthreads();
    for (int o = 256; o > 0; o >>= 1) {
        if (tid < o) sm[tid] = fmaxf(sm[tid], sm[tid + o]);
        __syncthreads();
    }
    const float bm = sm[0];
    __syncthreads();
    sm[tid] = expf(s - bm); __syncthreads();
    for (int o = 256; o > 0; o >>= 1) {
        if (tid < o) sm[tid] += sm[tid + o];
        __syncthreads();
    }
    if (tid == 0) { g_bm[blockIdx.x] = bm; g_bz[blockIdx.x] = sm[0]; }
}
__global__ void k_smax2() {
    __shared__ float m[64], z[64];
    const int tid = threadIdx.x;   // 64
    m[tid] = g_bm[tid]; z[tid] = g_bz[tid];
    __syncthreads();
    for (int o = 32; o > 0; o >>= 1) {
        if (tid < o) m[tid] = fmaxf(m[tid], m[tid + o]);
        __syncthreads();
    }
    const float M = m[0];
    __syncthreads();
    z[tid] *= expf(g_bm[tid] - M);
    __syncthreads();
    for (int o = 32; o > 0; o >>= 1) {
        if (tid < o) z[tid] += z[tid + o];
        __syncthreads();
    }
    if (tid == 0) { g_MZ[0] = M; g_MZ[1] = 1.0f / z[0]; }
}
__global__ __launch_bounds__(512) void k_smax3() {
    const int i = blockIdx.x * 512 + threadIdx.x;
    g_A[i] = expf(g_S[i] - g_MZ[0]) * g_MZ[1];
}

// ---------------- weighted pooling (deterministic two-stage) ----------------
__global__ __launch_bounds__(256) void k_pool(const float* __restrict__ V) {
    __shared__ float ash[512];
    const int tid = threadIdx.x;
    const int k   = blockIdx.x * 1024 + tid * 4;
    const int i0  = blockIdx.y * 512;
    for (int i = tid; i < 512; i += 256) ash[i] = g_A[i0 + i];
    __syncthreads();
    float4 acc = make_float4(0.f, 0.f, 0.f, 0.f);
    #pragma unroll 4
    for (int i = 0; i < 512; ++i) {
        float  a = ash[i];
        float4 v = *(const float4*)(V + (size_t)(i0 + i) * D + k);
        acc.x += a * v.x; acc.y += a * v.y;
        acc.z += a * v.z; acc.w += a * v.w;
    }
    *(float4*)&g_tp[blockIdx.y][k] = acc;
}
__global__ void k_pool_reduce() {
    const int k = blockIdx.x * blockDim.x + threadIdx.x;
    float s = 0.f;
    #pragma unroll
    for (int r = 0; r < 64; ++r) s += g_tp[r][k];
    g_t[k] = s;
}

// ---------------- final linear ----------------
__global__ void k_final(const float* __restrict__ W, float* __restrict__ out) {
    const int c    = threadIdx.y;
    const int lane = threadIdx.x;
    float s = 0.f;
    for (int k = lane; k < D; k += 32) s += W[c * D + k] * g_t[k];
    #pragma unroll
    for (int o = 16; o > 0; o >>= 1) s += __shfl_down_sync(0xffffffff, s, o);
    if (lane == 0) out[c] = s;
}

// ---------------- launcher ----------------
extern "C" void kernel_launch(void* const* d_in, const int* in_sizes, int n_in,
                              void* d_out, int out_size)
{
    const float* V  = (const float*)d_in[0];
    const float* U  = (const float*)d_in[1];
    const float* Wm = (const float*)d_in[2];
    const float* W  = (const float*)d_in[3];
    float* out = (float*)d_out;

    cudaFuncSetAttribute(k_scores_tc, cudaFuncAttributeMaxDynamicSharedMemorySize, SMEM_BYTES);

    k_packU<<<DP, 256>>>(U);
    k_packV<<<N_INST, 256>>>(V);
    k_scores_tc<<<dim3(128, 4), 512, SMEM_BYTES>>>(Wm);
    k_smax1<<<64, 512>>>();
    k_smax2<<<1, 64>>>();
    k_smax3<<<64, 512>>>();
    k_pool<<<dim3(2, 64), 256>>>(V);
    k_pool_reduce<<<2, 1024>>>();
    k_final<<<1, dim3(32, 4)>>>(W, out);
}

// round 6
// speedup vs baseline: 5.1860x; 5.1860x over previous
#include <cuda_runtime.h>
#include <cuda_fp16.h>
#include <math.h>
#include <stdint.h>

#define N_INST 32768
#define D      2048
#define DP     512
#define CLASSES 4

#define TM 256            // instances per CTA
#define TN 128            // j per CTA
#define NSTAGE 4          // smem buffers (3 in flight)
#define STG 49152         // 32KB A + 16KB B per stage
#define NSTOT 32          // 32 k-tiles, single fp16 pass

// ---------------- scratch (module-scope, no runtime allocation) ----------------
__device__ __align__(1024) uint8_t g_Vh[(size_t)N_INST * D * 2];   // fp16 V
__device__ __align__(1024) uint8_t g_Uh[DP * D * 2];               // fp16 U
__device__ float g_Sp[4][N_INST];   // per-j-tile logit partials
__device__ float g_S[N_INST];
__device__ float g_A[N_INST];
__device__ float g_bm[64], g_bz[64], g_MZ[2];
__device__ float g_tp[64][D];
__device__ float g_t[D];

// ---------------- PTX helpers (plain sm_80-era features only) ----------------
static __device__ __forceinline__ uint32_t smem_u32(const void* p) {
    uint32_t a;
    asm("{ .reg .u64 t; cvta.to.shared.u64 t, %1; cvt.u32.u64 %0, t; }" : "=r"(a) : "l"(p));
    return a;
}
static __device__ __forceinline__ void cp16(uint32_t dst, const void* src) {
    asm volatile("cp.async.cg.shared.global [%0], [%1], 16;" :: "r"(dst), "l"(src) : "memory");
}
static __device__ __forceinline__ void ldsm4(uint32_t* r, uint32_t addr) {
    asm volatile("ldmatrix.sync.aligned.m8n8.x4.shared.b16 {%0,%1,%2,%3}, [%4];"
                 : "=r"(r[0]), "=r"(r[1]), "=r"(r[2]), "=r"(r[3]) : "r"(addr));
}
static __device__ __forceinline__ void mma16816(float* d, const uint32_t* a, uint32_t b0, uint32_t b1) {
    asm volatile("mma.sync.aligned.m16n8k16.row.col.f32.f16.f16.f32 "
                 "{%0,%1,%2,%3}, {%4,%5,%6,%7}, {%8,%9}, {%0,%1,%2,%3};"
                 : "+f"(d[0]), "+f"(d[1]), "+f"(d[2]), "+f"(d[3])
                 : "r"(a[0]), "r"(a[1]), "r"(a[2]), "r"(a[3]), "r"(b0), "r"(b1));
}

// ---------------- pack kernels: fp32 -> fp16 ----------------
__global__ __launch_bounds__(256) void k_packV(const float* __restrict__ V) {
    uint32_t idx = blockIdx.x * 256 + threadIdx.x;   // 16,777,216 float4-quads
    float4 v = ((const float4*)V)[idx];
    __half2 h01 = __floats2half2_rn(v.x, v.y);
    __half2 h23 = __floats2half2_rn(v.z, v.w);
    ((uint2*)g_Vh)[idx] = make_uint2(*(uint32_t*)&h01, *(uint32_t*)&h23);
}
__global__ __launch_bounds__(256) void k_packU(const float* __restrict__ U) {
    uint32_t idx = blockIdx.x * 256 + threadIdx.x;   // 262,144 quads
    float4 v = ((const float4*)U)[idx];
    __half2 h01 = __floats2half2_rn(v.x, v.y);
    __half2 h23 = __floats2half2_rn(v.z, v.w);
    ((uint2*)g_Uh)[idx] = make_uint2(*(uint32_t*)&h01, *(uint32_t*)&h23);
}

// ---------------- main GEMM: C[256x128] tile, mma.sync fp16, fused w*tanh fold ----------------
// smem per stage: A[256 rows x 128B] (32KB) + B[128 rows x 128B] (16KB),
// xor-swizzled (bits[6:4] ^= row%8) for conflict-free ldmatrix.
#define SMEM_BYTES (NSTAGE * STG + 512 + 4096 + 1024)

__global__ __launch_bounds__(512, 1) void k_scores_tc(const float* __restrict__ Wm)
{
    extern __shared__ uint8_t dsm[];
    uint32_t raw = smem_u32(dsm);
    uint32_t sb  = (raw + 1023) & ~1023u;
    uint8_t* sp  = dsm + (sb - raw);
    float* Wsh   = (float*)(sp + NSTAGE * STG);
    float* part  = (float*)(sp + NSTAGE * STG + 512);   // [4][256]

    const int tid  = threadIdx.x;
    const int lane = tid & 31, wid = tid >> 5;
    const int wm = wid & 3, wn = wid >> 2;          // warp tile: rows wm*64, cols wn*32
    const int ibase = blockIdx.x * TM;
    const int jbase = blockIdx.y * TN;

    if (tid < TN) Wsh[tid] = Wm[jbase + tid];

    const uint8_t* aT = g_Vh + (size_t)ibase * (D * 2);
    const uint8_t* bT = g_Uh + (size_t)jbase * (D * 2);

    // cp.async loader constants (each thread: 4 A-chunks + 2 B-chunks of 16B)
    const uint32_t lrow   = tid >> 3;                       // 0..63
    const uint32_t lc16   = (tid & 7) * 16;
    const uint32_t ld_dst = lc16 ^ ((lrow & 7) << 4);       // swizzled col part

    // ldmatrix constants
    const uint32_t mask  = (lane & 7) << 4;
    const uint32_t aRow  = (wm * 64 + (lane & 15)) * 128;
    const uint32_t bRow  = (wn * 32 + (lane & 7) + ((lane >> 1) & 8)) * 128;
    const uint32_t kselA = (lane & 16);        // k-half select for A x4
    const uint32_t kselB = (lane & 8) << 1;    // k-half select for B x4

    float acc[4][4][4];
    #pragma unroll
    for (int a = 0; a < 4; ++a)
        #pragma unroll
        for (int b = 0; b < 4; ++b)
            #pragma unroll
            for (int c = 0; c < 4; ++c) acc[a][b][c] = 0.f;

    auto load_stage = [&](int s) {
        const int buf = s & (NSTAGE - 1);
        const uint8_t* as = aT + (size_t)s * 128;
        const uint8_t* bs = bT + (size_t)s * 128;
        const uint32_t dA = sb + buf * STG;
        const uint32_t dB = dA + 32768;
        #pragma unroll
        for (int q = 0; q < 4; ++q) {
            uint32_t row = lrow + q * 64;
            cp16(dA + row * 128 + ld_dst, as + (size_t)row * 4096 + lc16);
        }
        #pragma unroll
        for (int q = 0; q < 2; ++q) {
            uint32_t row = lrow + q * 64;
            cp16(dB + row * 128 + ld_dst, bs + (size_t)row * 4096 + lc16);
        }
        asm volatile("cp.async.commit_group;" ::: "memory");
    };

    load_stage(0); load_stage(1); load_stage(2);

    #pragma unroll 1
    for (int s = 0; s < NSTOT; ++s) {
        asm volatile("cp.async.wait_group 2;" ::: "memory");
        __syncthreads();
        const int buf = s & (NSTAGE - 1);
        const uint32_t smA = sb + buf * STG;
        const uint32_t smB = smA + 32768;

        #pragma unroll
        for (int kk = 0; kk < 4; ++kk) {
            const uint32_t kxA = (kk * 32 + kselA) ^ mask;
            const uint32_t kxB = (kk * 32 + kselB) ^ mask;
            uint32_t Af[4][4], Bf[2][4];
            #pragma unroll
            for (int mt = 0; mt < 4; ++mt) ldsm4(Af[mt], smA + aRow + mt * 2048 + kxA);
            #pragma unroll
            for (int p = 0; p < 2; ++p)   ldsm4(Bf[p],  smB + bRow + p  * 2048 + kxB);
            #pragma unroll
            for (int mt = 0; mt < 4; ++mt)
                #pragma unroll
                for (int nt = 0; nt < 4; ++nt) {
                    const uint32_t* B = Bf[nt >> 1];
                    mma16816(acc[mt][nt], Af[mt],
                             (nt & 1) ? B[2] : B[0], (nt & 1) ? B[3] : B[1]);
                }
        }
        if (s + 3 < NSTOT) load_stage(s + 3);
    }

    // ---- epilogue: s_part[i] = sum_{j in tile} w_j * tanh(c_ij) ----
    const int gr = lane >> 2;
    const int gc = (lane & 3) * 2;
    #pragma unroll
    for (int mt = 0; mt < 4; ++mt) {
        float l0 = 0.f, l1 = 0.f;
        #pragma unroll
        for (int nt = 0; nt < 4; ++nt) {
            int wi = wn * 32 + nt * 8 + gc;
            float w0 = Wsh[wi], w1 = Wsh[wi + 1];
            l0 += w0 * tanhf(acc[mt][nt][0]) + w1 * tanhf(acc[mt][nt][1]);
            l1 += w0 * tanhf(acc[mt][nt][2]) + w1 * tanhf(acc[mt][nt][3]);
        }
        l0 += __shfl_xor_sync(0xffffffffu, l0, 1);
        l0 += __shfl_xor_sync(0xffffffffu, l0, 2);
        l1 += __shfl_xor_sync(0xffffffffu, l1, 1);
        l1 += __shfl_xor_sync(0xffffffffu, l1, 2);
        if ((lane & 3) == 0) {
            part[wn * 256 + wm * 64 + mt * 16 + gr]     = l0;
            part[wn * 256 + wm * 64 + mt * 16 + 8 + gr] = l1;
        }
    }
    __syncthreads();
    if (tid < 256) {
        float sv = part[tid] + part[256 + tid] + part[512 + tid] + part[768 + tid];
        g_Sp[blockIdx.y][ibase + tid] = sv;
    }
}

// ---------------- parallel softmax (3 tiny kernels) ----------------
__global__ __launch_bounds__(512) void k_smax1() {
    __shared__ float sm[512];
    const int tid = threadIdx.x;
    const int i = blockIdx.x * 512 + tid;
    float s = g_Sp[0][i] + g_Sp[1][i] + g_Sp[2][i] + g_Sp[3][i];
    g_S[i] = s;
    sm[tid] = s; __syncthreads();
    for (int o = 256; o > 0; o >>= 1) {
        if (tid < o) sm[tid] = fmaxf(sm[tid], sm[tid + o]);
        __syncthreads();
    }
    const float bm = sm[0];
    __syncthreads();
    sm[tid] = expf(s - bm); __syncthreads();
    for (int o = 256; o > 0; o >>= 1) {
        if (tid < o) sm[tid] += sm[tid + o];
        __syncthreads();
    }
    if (tid == 0) { g_bm[blockIdx.x] = bm; g_bz[blockIdx.x] = sm[0]; }
}
__global__ void k_smax2() {
    __shared__ float m[64], z[64];
    const int tid = threadIdx.x;   // 64
    m[tid] = g_bm[tid]; z[tid] = g_bz[tid];
    __syncthreads();
    for (int o = 32; o > 0; o >>= 1) {
        if (tid < o) m[tid] = fmaxf(m[tid], m[tid + o]);
        __syncthreads();
    }
    const float M = m[0];
    __syncthreads();
    z[tid] *= expf(g_bm[tid] - M);
    __syncthreads();
    for (int o = 32; o > 0; o >>= 1) {
        if (tid < o) z[tid] += z[tid + o];
        __syncthreads();
    }
    if (tid == 0) { g_MZ[0] = M; g_MZ[1] = 1.0f / z[0]; }
}
__global__ __launch_bounds__(512) void k_smax3() {
    const int i = blockIdx.x * 512 + threadIdx.x;
    g_A[i] = expf(g_S[i] - g_MZ[0]) * g_MZ[1];
}

// ---------------- weighted pooling (deterministic two-stage, fp32 V) ----------------
__global__ __launch_bounds__(256) void k_pool(const float* __restrict__ V) {
    __shared__ float ash[512];
    const int tid = threadIdx.x;
    const int k   = blockIdx.x * 1024 + tid * 4;
    const int i0  = blockIdx.y * 512;
    for (int i = tid; i < 512; i += 256) ash[i] = g_A[i0 + i];
    __syncthreads();
    float4 acc = make_float4(0.f, 0.f, 0.f, 0.f);
    #pragma unroll 4
    for (int i = 0; i < 512; ++i) {
        float  a = ash[i];
        float4 v = *(const float4*)(V + (size_t)(i0 + i) * D + k);
        acc.x += a * v.x; acc.y += a * v.y;
        acc.z += a * v.z; acc.w += a * v.w;
    }
    *(float4*)&g_tp[blockIdx.y][k] = acc;
}
__global__ void k_pool_reduce() {
    const int k = blockIdx.x * blockDim.x + threadIdx.x;
    float s = 0.f;
    #pragma unroll
    for (int r = 0; r < 64; ++r) s += g_tp[r][k];
    g_t[k] = s;
}

// ---------------- final linear ----------------
__global__ void k_final(const float* __restrict__ W, float* __restrict__ out) {
    const int c    = threadIdx.y;
    const int lane = threadIdx.x;
    float s = 0.f;
    for (int k = lane; k < D; k += 32) s += W[c * D + k] * g_t[k];
    #pragma unroll
    for (int o = 16; o > 0; o >>= 1) s += __shfl_down_sync(0xffffffff, s, o);
    if (lane == 0) out[c] = s;
}

// ---------------- launcher ----------------
extern "C" void kernel_launch(void* const* d_in, const int* in_sizes, int n_in,
                              void* d_out, int out_size)
{
    const float* V  = (const float*)d_in[0];   // V_prime [32768, 2048]
    const float* U  = (const float*)d_in[1];   // U_t     [512, 2048]
    const float* Wm = (const float*)d_in[2];   // W_mta   [1, 512]
    const float* W  = (const float*)d_in[3];   // W       [4, 2048]
    float* out = (float*)d_out;

    cudaFuncSetAttribute(k_scores_tc, cudaFuncAttributeMaxDynamicSharedMemorySize, SMEM_BYTES);

    k_packU<<<1024, 256>>>(U);
    k_packV<<<65536, 256>>>(V);
    k_scores_tc<<<dim3(128, 4), 512, SMEM_BYTES>>>(Wm);
    k_smax1<<<64, 512>>>();
    k_smax2<<<1, 64>>>();
    k_smax3<<<64, 512>>>();
    k_pool<<<dim3(2, 64), 256>>>(V);
    k_pool_reduce<<<2, 1024>>>();
    k_final<<<1, dim3(32, 4)>>>(W, out);
}